// round 10
// baseline (speedup 1.0000x reference)
#include <cuda_runtime.h>
#include <cuda_fp16.h>

// Problem constants: N=100000, F=16, E=3200000, H=64
#define NN 100000
#define FF 16
#define EE 3200000
#define HH 64

// fp16 scratch tables, one 128-byte row per node (64 halves).
// P[n][j] = sum_k x[n][k]*W1[k][j] + b1[j]   (dst half of concat)
// Q[n][j] = sum_k x[n][k]*W1[16+k][j]        (src half of concat)
__device__ uint4 g_Ph[(size_t)NN * (HH / 8)];   // 12.8 MB
__device__ uint4 g_Qh[(size_t)NN * (HH / 8)];

// ---------------------------------------------------------------------------
// Kernel 1: precompute P,Q in fp16. 4 nodes per thread so every smem weight
// read (LDS.64) is reused 4x.
// ---------------------------------------------------------------------------
__global__ void __launch_bounds__(256)
precompute_kernel(const float* __restrict__ x,
                  const float* __restrict__ W1,
                  const float* __restrict__ b1)
{
    __shared__ float sW1[2 * FF * HH];   // 8 KB
    __shared__ float sb1[HH];
    for (int i = threadIdx.x; i < 2 * FF * HH; i += blockDim.x) sW1[i] = W1[i];
    if (threadIdx.x < HH) sb1[threadIdx.x] = b1[threadIdx.x];
    __syncthreads();

    const int total  = (NN / 4) * 32;                // 800K (node-quad, jp)
    const int stride = gridDim.x * blockDim.x;
    for (int idx = blockIdx.x * blockDim.x + threadIdx.x; idx < total; idx += stride) {
        int nq = idx >> 5;            // node quad (warp = one quad)
        int jp = idx & 31;            // half2 column pair
        int n0 = nq * 4;

        float bias0 = sb1[2 * jp], bias1 = sb1[2 * jp + 1];
        float p0[4], p1[4], q0[4], q1[4];
#pragma unroll
        for (int nn = 0; nn < 4; nn++) {
            p0[nn] = bias0; p1[nn] = bias1; q0[nn] = 0.0f; q1[nn] = 0.0f;
        }

#pragma unroll
        for (int kc = 0; kc < 4; kc++) {             // k chunk of 4
            float4 xv[4];
#pragma unroll
            for (int nn = 0; nn < 4; nn++)
                xv[nn] = __ldg((const float4*)(x + (n0 + nn) * FF) + kc);
#pragma unroll
            for (int kk = 0; kk < 4; kk++) {
                int k = kc * 4 + kk;
                float2 wp = ((const float2*)(sW1 + k * HH))[jp];
                float2 wq = ((const float2*)(sW1 + (FF + k) * HH))[jp];
#pragma unroll
                for (int nn = 0; nn < 4; nn++) {
                    float xs = (kk == 0) ? xv[nn].x : (kk == 1) ? xv[nn].y
                             : (kk == 2) ? xv[nn].z : xv[nn].w;
                    p0[nn] = fmaf(xs, wp.x, p0[nn]);
                    p1[nn] = fmaf(xs, wp.y, p1[nn]);
                    q0[nn] = fmaf(xs, wq.x, q0[nn]);
                    q1[nn] = fmaf(xs, wq.y, q1[nn]);
                }
            }
        }
#pragma unroll
        for (int nn = 0; nn < 4; nn++) {
            int o = (n0 + nn) * 32 + jp;
            ((__half2*)g_Ph)[o] = __floats2half2_rn(p0[nn], p1[nn]);
            ((__half2*)g_Qh)[o] = __floats2half2_rn(q0[nn], q1[nn]);
        }
    }
}

// ---------------------------------------------------------------------------
// Kernel 2: 8 lanes per group, 2 edges per group. Packed half2 dots,
// 32-bit address arithmetic throughout, 6-shuffle reduction:
// select-swap at m=4 first, then 2 butterfly rounds on the owned pair.
// ---------------------------------------------------------------------------
__global__ void __launch_bounds__(256)
edge_kernel(const float* __restrict__ x,
            const int* __restrict__ ei,        // [2, E] int32: row0=src, row1=dst
            const float* __restrict__ W2,      // [64,2] row-major
            const float* __restrict__ b2,      // [2]
            float* __restrict__ out)           // [E,16]
{
    __shared__ __half2 sWa[HH / 2];            // (wa_{2i}, wa_{2i+1}), 128B
    __shared__ __half2 sWb[HH / 2];            // (wb_{2i}, wb_{2i+1}), 128B
    if (threadIdx.x < 32) {
        int i = threadIdx.x;
        sWa[i] = __floats2half2_rn(W2[4 * i + 0], W2[4 * i + 2]);
        sWb[i] = __floats2half2_rn(W2[4 * i + 1], W2[4 * i + 3]);
    }
    __syncthreads();

    unsigned tid = blockIdx.x * blockDim.x + threadIdx.x;
    int grp = (int)(tid >> 3);           // group = 2 consecutive edges (<1.6M)
    int sub = (int)(tid & 7);
    if (grp >= (EE >> 1)) return;

    // ---- index loads (int2: e0,e1 adjacent) ----
    int2 s01 = __ldg((const int2*)ei + grp);                 // src of e0,e1
    int2 d01 = __ldg((const int2*)ei + (EE >> 1) + grp);     // dst of e0,e1

    // ---- front-batched gathers (32-bit offsets) ----
    uint4 pu0 = g_Ph[d01.x * (HH / 8) + sub];
    uint4 qu0 = g_Qh[s01.x * (HH / 8) + sub];
    uint4 pu1 = g_Ph[d01.y * (HH / 8) + sub];
    uint4 qu1 = g_Qh[s01.y * (HH / 8) + sub];

    bool lo = (sub < 4);
    int dN = lo ? d01.x : d01.y;
    int sN = lo ? s01.x : s01.y;
    int c  = sub & 3;
    float4 xd = __ldg((const float4*)(x + dN * FF) + c);
    float4 xs = __ldg((const float4*)(x + sN * FF) + c);

    // ---- weights for this lane's j = 8*sub .. 8*sub+7 (1 LDS.128 each) ----
    uint4 wau = *(const uint4*)(sWa + 4 * sub);
    uint4 wbu = *(const uint4*)(sWb + 4 * sub);
    const __half2* wa = (const __half2*)&wau;
    const __half2* wb = (const __half2*)&wbu;

    // ---- packed half2 dots ----
    const __half2* ph0 = (const __half2*)&pu0;
    const __half2* qh0 = (const __half2*)&qu0;
    const __half2* ph1 = (const __half2*)&pu1;
    const __half2* qh1 = (const __half2*)&qu1;
    const __half2 z2 = __float2half2_rn(0.0f);
    __half2 avh0 = z2, bvh0 = z2, avh1 = z2, bvh1 = z2;
#pragma unroll
    for (int t = 0; t < 4; t++) {
        __half2 hh0 = __hmax2(__hadd2(ph0[t], qh0[t]), z2);
        __half2 hh1 = __hmax2(__hadd2(ph1[t], qh1[t]), z2);
        avh0 = __hfma2(hh0, wa[t], avh0);
        bvh0 = __hfma2(hh0, wb[t], bvh0);
        avh1 = __hfma2(hh1, wa[t], avh1);
        bvh1 = __hfma2(hh1, wb[t], bvh1);
    }
    float2 fa0 = __half22float2(avh0);
    float2 fb0 = __half22float2(bvh0);
    float2 fa1 = __half22float2(avh1);
    float2 fb1 = __half22float2(bvh1);
    float av0 = fa0.x + fa0.y, bv0 = fb0.x + fb0.y;
    float av1 = fa1.x + fa1.y, bv1 = fb1.x + fb1.y;

    // ---- reduction: swap-first (m=4), then butterfly m=1,2 on owned pair ----
    // lane owns e0 if lo, e1 if hi; it sends its partial for the other edge.
    float a = lo ? av0 : av1;
    float b = lo ? bv0 : bv1;
    float oa = lo ? av1 : av0;
    float ob = lo ? bv1 : bv0;
    a += __shfl_xor_sync(0xffffffffu, oa, 4);
    b += __shfl_xor_sync(0xffffffffu, ob, 4);
#pragma unroll
    for (int m = 1; m < 4; m <<= 1) {
        a += __shfl_xor_sync(0xffffffffu, a, m);
        b += __shfl_xor_sync(0xffffffffu, b, m);
    }
    a += b2[0];
    b += b2[1];

    // ---- epilogue: lane owns 4 floats of its edge's 16-float output ----
    int e = grp * 2 + (lo ? 0 : 1);
    float4 o;
    o.x = a * (xd.x - b * xs.x);
    o.y = a * (xd.y - b * xs.y);
    o.z = a * (xd.z - b * xs.z);
    o.w = a * (xd.w - b * xs.w);
    ((float4*)(out + e * FF))[c] = o;
}

// ---------------------------------------------------------------------------
// Launch
// ---------------------------------------------------------------------------
extern "C" void kernel_launch(void* const* d_in, const int* in_sizes, int n_in,
                              void* d_out, int out_size)
{
    const float* x   = (const float*)d_in[0];   // [N,16]
    const int*   ei  = (const int*)d_in[1];     // [2,E] int32
    const float* W1  = (const float*)d_in[2];   // [32,64]
    const float* b1  = (const float*)d_in[3];   // [64]
    const float* W2  = (const float*)d_in[4];   // [64,2]
    const float* b2  = (const float*)d_in[5];   // [2]
    float*       out = (float*)d_out;           // [E,16]

    (void)in_sizes; (void)n_in; (void)out_size;

    precompute_kernel<<<1184, 256>>>(x, W1, b1);

    {
        long long total = (long long)(EE / 2) * 8;   // 12.8M threads
        int threads = 256;
        int blocks = (int)((total + threads - 1) / threads);
        edge_kernel<<<blocks, threads>>>(x, ei, W2, b2, out);
    }
}

// round 11
// speedup vs baseline: 1.0133x; 1.0133x over previous
#include <cuda_runtime.h>
#include <cuda_fp16.h>

// Problem constants: N=100000, F=16, E=3200000, H=64
#define NN 100000
#define FF 16
#define EE 3200000
#define HH 64

// fp16 scratch tables, one 128-byte row per node (64 halves).
// P[n][j] = sum_k x[n][k]*W1[k][j] + b1[j]   (dst half of concat)
// Q[n][j] = sum_k x[n][k]*W1[16+k][j]        (src half of concat)
__device__ uint4 g_Ph[(size_t)NN * (HH / 8)];   // 12.8 MB
__device__ uint4 g_Qh[(size_t)NN * (HH / 8)];

// ---------------------------------------------------------------------------
// Kernel 1: precompute P,Q in fp16. 4 nodes per thread so every smem weight
// read (LDS.64) is reused 4x.
// ---------------------------------------------------------------------------
__global__ void __launch_bounds__(256)
precompute_kernel(const float* __restrict__ x,
                  const float* __restrict__ W1,
                  const float* __restrict__ b1)
{
    __shared__ float sW1[2 * FF * HH];   // 8 KB
    __shared__ float sb1[HH];
    for (int i = threadIdx.x; i < 2 * FF * HH; i += blockDim.x) sW1[i] = W1[i];
    if (threadIdx.x < HH) sb1[threadIdx.x] = b1[threadIdx.x];
    __syncthreads();

    const int total  = (NN / 4) * 32;                // 800K (node-quad, jp)
    const int stride = gridDim.x * blockDim.x;
    for (int idx = blockIdx.x * blockDim.x + threadIdx.x; idx < total; idx += stride) {
        int nq = idx >> 5;            // node quad (warp = one quad)
        int jp = idx & 31;            // half2 column pair
        int n0 = nq * 4;

        float bias0 = sb1[2 * jp], bias1 = sb1[2 * jp + 1];
        float p0[4], p1[4], q0[4], q1[4];
#pragma unroll
        for (int nn = 0; nn < 4; nn++) {
            p0[nn] = bias0; p1[nn] = bias1; q0[nn] = 0.0f; q1[nn] = 0.0f;
        }

#pragma unroll
        for (int kc = 0; kc < 4; kc++) {             // k chunk of 4
            float4 xv[4];
#pragma unroll
            for (int nn = 0; nn < 4; nn++)
                xv[nn] = ((const float4*)(x + (n0 + nn) * FF))[kc];
#pragma unroll
            for (int kk = 0; kk < 4; kk++) {
                int k = kc * 4 + kk;
                float2 wp = ((const float2*)(sW1 + k * HH))[jp];
                float2 wq = ((const float2*)(sW1 + (FF + k) * HH))[jp];
#pragma unroll
                for (int nn = 0; nn < 4; nn++) {
                    float xs = (kk == 0) ? xv[nn].x : (kk == 1) ? xv[nn].y
                             : (kk == 2) ? xv[nn].z : xv[nn].w;
                    p0[nn] = fmaf(xs, wp.x, p0[nn]);
                    p1[nn] = fmaf(xs, wp.y, p1[nn]);
                    q0[nn] = fmaf(xs, wq.x, q0[nn]);
                    q1[nn] = fmaf(xs, wq.y, q1[nn]);
                }
            }
        }
#pragma unroll
        for (int nn = 0; nn < 4; nn++) {
            int o = (n0 + nn) * 32 + jp;
            ((__half2*)g_Ph)[o] = __floats2half2_rn(p0[nn], p1[nn]);
            ((__half2*)g_Qh)[o] = __floats2half2_rn(q0[nn], q1[nn]);
        }
    }
}

// ---------------------------------------------------------------------------
// Kernel 2: 8 lanes per group, 2 edges per group. Packed half2 dots,
// 32-bit addressing, 6-shuffle reduction. __launch_bounds__(256,8) pins the
// register budget to 32 so occupancy stays at 8 CTAs/SM (the R10 regression
// was a 38-reg / 6-CTA occupancy loss).
// ---------------------------------------------------------------------------
__global__ void __launch_bounds__(256, 8)
edge_kernel(const float* __restrict__ x,
            const int* __restrict__ ei,        // [2, E] int32: row0=src, row1=dst
            const float* __restrict__ W2,      // [64,2] row-major
            const float* __restrict__ b2,      // [2]
            float* __restrict__ out)           // [E,16]
{
    __shared__ __half2 sWa[HH / 2];            // (wa_{2i}, wa_{2i+1}), 128B
    __shared__ __half2 sWb[HH / 2];            // (wb_{2i}, wb_{2i+1}), 128B
    if (threadIdx.x < 32) {
        int i = threadIdx.x;
        sWa[i] = __floats2half2_rn(W2[4 * i + 0], W2[4 * i + 2]);
        sWb[i] = __floats2half2_rn(W2[4 * i + 1], W2[4 * i + 3]);
    }
    __syncthreads();

    unsigned tid = blockIdx.x * blockDim.x + threadIdx.x;
    int grp = (int)(tid >> 3);           // group = 2 consecutive edges (<1.6M)
    int sub = (int)(tid & 7);
    if (grp >= (EE >> 1)) return;

    // ---- index loads (int2: e0,e1 adjacent) ----
    int2 s01 = ((const int2*)ei)[grp];                 // src of e0,e1
    int2 d01 = ((const int2*)ei)[(EE >> 1) + grp];     // dst of e0,e1

    // ---- front-batched gathers (32-bit offsets) ----
    uint4 pu0 = g_Ph[d01.x * (HH / 8) + sub];
    uint4 qu0 = g_Qh[s01.x * (HH / 8) + sub];
    uint4 pu1 = g_Ph[d01.y * (HH / 8) + sub];
    uint4 qu1 = g_Qh[s01.y * (HH / 8) + sub];

    bool lo = (sub < 4);
    int dN = lo ? d01.x : d01.y;
    int sN = lo ? s01.x : s01.y;
    int c  = sub & 3;
    float4 xd = ((const float4*)(x + dN * FF))[c];
    float4 xs = ((const float4*)(x + sN * FF))[c];

    // ---- weights for this lane's j = 8*sub .. 8*sub+7 (1 LDS.128 each) ----
    uint4 wau = *(const uint4*)(sWa + 4 * sub);
    uint4 wbu = *(const uint4*)(sWb + 4 * sub);
    const __half2* wa = (const __half2*)&wau;
    const __half2* wb = (const __half2*)&wbu;

    // ---- packed half2 dots ----
    const __half2* ph0 = (const __half2*)&pu0;
    const __half2* qh0 = (const __half2*)&qu0;
    const __half2* ph1 = (const __half2*)&pu1;
    const __half2* qh1 = (const __half2*)&qu1;
    const __half2 z2 = __float2half2_rn(0.0f);
    __half2 avh0 = z2, bvh0 = z2, avh1 = z2, bvh1 = z2;
#pragma unroll
    for (int t = 0; t < 4; t++) {
        __half2 hh0 = __hmax2(__hadd2(ph0[t], qh0[t]), z2);
        __half2 hh1 = __hmax2(__hadd2(ph1[t], qh1[t]), z2);
        avh0 = __hfma2(hh0, wa[t], avh0);
        bvh0 = __hfma2(hh0, wb[t], bvh0);
        avh1 = __hfma2(hh1, wa[t], avh1);
        bvh1 = __hfma2(hh1, wb[t], bvh1);
    }
    float2 fa0 = __half22float2(avh0);
    float2 fb0 = __half22float2(bvh0);
    float2 fa1 = __half22float2(avh1);
    float2 fb1 = __half22float2(bvh1);
    float av0 = fa0.x + fa0.y, bv0 = fb0.x + fb0.y;
    float av1 = fa1.x + fa1.y, bv1 = fb1.x + fb1.y;

    // ---- reduction: swap-first (m=4), then butterfly m=1,2 on owned pair ----
    float a  = lo ? av0 : av1;
    float b  = lo ? bv0 : bv1;
    float oa = lo ? av1 : av0;
    float ob = lo ? bv1 : bv0;
    a += __shfl_xor_sync(0xffffffffu, oa, 4);
    b += __shfl_xor_sync(0xffffffffu, ob, 4);
#pragma unroll
    for (int m = 1; m < 4; m <<= 1) {
        a += __shfl_xor_sync(0xffffffffu, a, m);
        b += __shfl_xor_sync(0xffffffffu, b, m);
    }
    a += b2[0];
    b += b2[1];

    // ---- epilogue: lane owns 4 floats of its edge's 16-float output ----
    int e = grp * 2 + (lo ? 0 : 1);
    float4 o;
    o.x = a * (xd.x - b * xs.x);
    o.y = a * (xd.y - b * xs.y);
    o.z = a * (xd.z - b * xs.z);
    o.w = a * (xd.w - b * xs.w);
    ((float4*)(out + e * FF))[c] = o;
}

// ---------------------------------------------------------------------------
// Launch
// ---------------------------------------------------------------------------
extern "C" void kernel_launch(void* const* d_in, const int* in_sizes, int n_in,
                              void* d_out, int out_size)
{
    const float* x   = (const float*)d_in[0];   // [N,16]
    const int*   ei  = (const int*)d_in[1];     // [2,E] int32
    const float* W1  = (const float*)d_in[2];   // [32,64]
    const float* b1  = (const float*)d_in[3];   // [64]
    const float* W2  = (const float*)d_in[4];   // [64,2]
    const float* b2  = (const float*)d_in[5];   // [2]
    float*       out = (float*)d_out;           // [E,16]

    (void)in_sizes; (void)n_in; (void)out_size;

    precompute_kernel<<<1184, 256>>>(x, W1, b1);

    {
        long long total = (long long)(EE / 2) * 8;   // 12.8M threads
        int threads = 256;
        int blocks = (int)((total + threads - 1) / threads);
        edge_kernel<<<blocks, threads>>>(x, ei, W2, b2, out);
    }
}

// round 12
// speedup vs baseline: 1.0142x; 1.0009x over previous
#include <cuda_runtime.h>
#include <cuda_fp16.h>

// Problem constants: N=100000, F=16, E=3200000, H=64
#define NN 100000
#define FF 16
#define EE 3200000
#define HH 64

// fp16 scratch tables, one 128-byte row per node (64 halves).
// P[n][j] = sum_k x[n][k]*W1[k][j] + b1[j]   (dst half of concat)
// Q[n][j] = sum_k x[n][k]*W1[16+k][j]        (src half of concat)
__device__ uint4 g_Ph[(size_t)NN * (HH / 8)];   // 12.8 MB
__device__ uint4 g_Qh[(size_t)NN * (HH / 8)];

// ---------------------------------------------------------------------------
// Kernel 1: precompute P,Q in fp16. 4 nodes per thread so every smem weight
// read (LDS.64) is reused 4x.
// ---------------------------------------------------------------------------
__global__ void __launch_bounds__(256)
precompute_kernel(const float* __restrict__ x,
                  const float* __restrict__ W1,
                  const float* __restrict__ b1)
{
    __shared__ float sW1[2 * FF * HH];   // 8 KB
    __shared__ float sb1[HH];
    for (int i = threadIdx.x; i < 2 * FF * HH; i += blockDim.x) sW1[i] = W1[i];
    if (threadIdx.x < HH) sb1[threadIdx.x] = b1[threadIdx.x];
    __syncthreads();

    const int total  = (NN / 4) * 32;                // 800K (node-quad, jp)
    const int stride = gridDim.x * blockDim.x;
    for (int idx = blockIdx.x * blockDim.x + threadIdx.x; idx < total; idx += stride) {
        int nq = idx >> 5;            // node quad (warp = one quad)
        int jp = idx & 31;            // half2 column pair
        int n0 = nq * 4;

        float bias0 = sb1[2 * jp], bias1 = sb1[2 * jp + 1];
        float p0[4], p1[4], q0[4], q1[4];
#pragma unroll
        for (int nn = 0; nn < 4; nn++) {
            p0[nn] = bias0; p1[nn] = bias1; q0[nn] = 0.0f; q1[nn] = 0.0f;
        }

#pragma unroll
        for (int kc = 0; kc < 4; kc++) {             // k chunk of 4
            float4 xv[4];
#pragma unroll
            for (int nn = 0; nn < 4; nn++)
                xv[nn] = ((const float4*)(x + (n0 + nn) * FF))[kc];
#pragma unroll
            for (int kk = 0; kk < 4; kk++) {
                int k = kc * 4 + kk;
                float2 wp = ((const float2*)(sW1 + k * HH))[jp];
                float2 wq = ((const float2*)(sW1 + (FF + k) * HH))[jp];
#pragma unroll
                for (int nn = 0; nn < 4; nn++) {
                    float xs = (kk == 0) ? xv[nn].x : (kk == 1) ? xv[nn].y
                             : (kk == 2) ? xv[nn].z : xv[nn].w;
                    p0[nn] = fmaf(xs, wp.x, p0[nn]);
                    p1[nn] = fmaf(xs, wp.y, p1[nn]);
                    q0[nn] = fmaf(xs, wq.x, q0[nn]);
                    q1[nn] = fmaf(xs, wq.y, q1[nn]);
                }
            }
        }
#pragma unroll
        for (int nn = 0; nn < 4; nn++) {
            int o = (n0 + nn) * 32 + jp;
            ((__half2*)g_Ph)[o] = __floats2half2_rn(p0[nn], p1[nn]);
            ((__half2*)g_Qh)[o] = __floats2half2_rn(q0[nn], q1[nn]);
        }
    }
}

// ---------------------------------------------------------------------------
// Kernel 2: 8 lanes per group, 2 edges per group. Packed half2 dots,
// 32-bit addressing, 6-shuffle reduction, regs pinned to 32.
// NEW: all gathers use __ldcg (no L1 line allocation -> no fill traffic;
// L1 hit rate on these random rows is ~0 anyway) and output uses __stwt
// (streaming store, no L2 allocation for the 205MB write-once buffer).
// ---------------------------------------------------------------------------
__global__ void __launch_bounds__(256, 8)
edge_kernel(const float* __restrict__ x,
            const int* __restrict__ ei,        // [2, E] int32: row0=src, row1=dst
            const float* __restrict__ W2,      // [64,2] row-major
            const float* __restrict__ b2,      // [2]
            float* __restrict__ out)           // [E,16]
{
    __shared__ __half2 sWa[HH / 2];            // (wa_{2i}, wa_{2i+1}), 128B
    __shared__ __half2 sWb[HH / 2];            // (wb_{2i}, wb_{2i+1}), 128B
    if (threadIdx.x < 32) {
        int i = threadIdx.x;
        sWa[i] = __floats2half2_rn(W2[4 * i + 0], W2[4 * i + 2]);
        sWb[i] = __floats2half2_rn(W2[4 * i + 1], W2[4 * i + 3]);
    }
    __syncthreads();

    unsigned tid = blockIdx.x * blockDim.x + threadIdx.x;
    int grp = (int)(tid >> 3);           // group = 2 consecutive edges (<1.6M)
    int sub = (int)(tid & 7);
    if (grp >= (EE >> 1)) return;

    // ---- index loads (int2: e0,e1 adjacent) ----
    int2 s01 = __ldcg((const int2*)ei + grp);                 // src of e0,e1
    int2 d01 = __ldcg((const int2*)ei + (EE >> 1) + grp);     // dst of e0,e1

    // ---- front-batched gathers (32-bit offsets, L2-only caching) ----
    uint4 pu0 = __ldcg(g_Ph + d01.x * (HH / 8) + sub);
    uint4 qu0 = __ldcg(g_Qh + s01.x * (HH / 8) + sub);
    uint4 pu1 = __ldcg(g_Ph + d01.y * (HH / 8) + sub);
    uint4 qu1 = __ldcg(g_Qh + s01.y * (HH / 8) + sub);

    bool lo = (sub < 4);
    int dN = lo ? d01.x : d01.y;
    int sN = lo ? s01.x : s01.y;
    int c  = sub & 3;
    float4 xd = __ldcg((const float4*)(x + dN * FF) + c);
    float4 xs = __ldcg((const float4*)(x + sN * FF) + c);

    // ---- weights for this lane's j = 8*sub .. 8*sub+7 (1 LDS.128 each) ----
    uint4 wau = *(const uint4*)(sWa + 4 * sub);
    uint4 wbu = *(const uint4*)(sWb + 4 * sub);
    const __half2* wa = (const __half2*)&wau;
    const __half2* wb = (const __half2*)&wbu;

    // ---- packed half2 dots ----
    const __half2* ph0 = (const __half2*)&pu0;
    const __half2* qh0 = (const __half2*)&qu0;
    const __half2* ph1 = (const __half2*)&pu1;
    const __half2* qh1 = (const __half2*)&qu1;
    const __half2 z2 = __float2half2_rn(0.0f);
    __half2 avh0 = z2, bvh0 = z2, avh1 = z2, bvh1 = z2;
#pragma unroll
    for (int t = 0; t < 4; t++) {
        __half2 hh0 = __hmax2(__hadd2(ph0[t], qh0[t]), z2);
        __half2 hh1 = __hmax2(__hadd2(ph1[t], qh1[t]), z2);
        avh0 = __hfma2(hh0, wa[t], avh0);
        bvh0 = __hfma2(hh0, wb[t], bvh0);
        avh1 = __hfma2(hh1, wa[t], avh1);
        bvh1 = __hfma2(hh1, wb[t], bvh1);
    }
    float2 fa0 = __half22float2(avh0);
    float2 fb0 = __half22float2(bvh0);
    float2 fa1 = __half22float2(avh1);
    float2 fb1 = __half22float2(bvh1);
    float av0 = fa0.x + fa0.y, bv0 = fb0.x + fb0.y;
    float av1 = fa1.x + fa1.y, bv1 = fb1.x + fb1.y;

    // ---- reduction: swap-first (m=4), then butterfly m=1,2 on owned pair ----
    float a  = lo ? av0 : av1;
    float b  = lo ? bv0 : bv1;
    float oa = lo ? av1 : av0;
    float ob = lo ? bv1 : bv0;
    a += __shfl_xor_sync(0xffffffffu, oa, 4);
    b += __shfl_xor_sync(0xffffffffu, ob, 4);
#pragma unroll
    for (int m = 1; m < 4; m <<= 1) {
        a += __shfl_xor_sync(0xffffffffu, a, m);
        b += __shfl_xor_sync(0xffffffffu, b, m);
    }
    a += b2[0];
    b += b2[1];

    // ---- epilogue: lane owns 4 floats of its edge's 16-float output ----
    int e = grp * 2 + (lo ? 0 : 1);
    float4 o;
    o.x = a * (xd.x - b * xs.x);
    o.y = a * (xd.y - b * xs.y);
    o.z = a * (xd.z - b * xs.z);
    o.w = a * (xd.w - b * xs.w);
    __stwt((float4*)(out + e * FF) + c, o);
}

// ---------------------------------------------------------------------------
// Launch
// ---------------------------------------------------------------------------
extern "C" void kernel_launch(void* const* d_in, const int* in_sizes, int n_in,
                              void* d_out, int out_size)
{
    const float* x   = (const float*)d_in[0];   // [N,16]
    const int*   ei  = (const int*)d_in[1];     // [2,E] int32
    const float* W1  = (const float*)d_in[2];   // [32,64]
    const float* b1  = (const float*)d_in[3];   // [64]
    const float* W2  = (const float*)d_in[4];   // [64,2]
    const float* b2  = (const float*)d_in[5];   // [2]
    float*       out = (float*)d_out;           // [E,16]

    (void)in_sizes; (void)n_in; (void)out_size;

    precompute_kernel<<<1184, 256>>>(x, W1, b1);

    {
        long long total = (long long)(EE / 2) * 8;   // 12.8M threads
        int threads = 256;
        int blocks = (int)((total + threads - 1) / threads);
        edge_kernel<<<blocks, threads>>>(x, ei, W2, b2, out);
    }
}

// round 13
// speedup vs baseline: 1.0161x; 1.0019x over previous
#include <cuda_runtime.h>
#include <cuda_fp16.h>

// Problem constants: N=100000, F=16, E=3200000, H=64
#define NN 100000
#define FF 16
#define EE 3200000
#define HH 64

// fp16 scratch tables, one 128-byte row per node (64 halves).
// P[n][j] = sum_k x[n][k]*W1[k][j] + b1[j]   (dst half of concat)
// Q[n][j] = sum_k x[n][k]*W1[16+k][j]        (src half of concat)
__device__ uint4 g_Ph[(size_t)NN * (HH / 8)];   // 12.8 MB
__device__ uint4 g_Qh[(size_t)NN * (HH / 8)];
// fp16 copy of x: 16 halves = 32B per node, lane c owns halves 4c..4c+3.
__device__ uint2 g_Xh[(size_t)NN * 4];          // 3.2 MB

// ---------------------------------------------------------------------------
// Kernel 1: precompute P,Q (and fp16 x copy). 4 nodes per thread so every
// smem weight read (LDS.64) is reused 4x.
// ---------------------------------------------------------------------------
__global__ void __launch_bounds__(256)
precompute_kernel(const float* __restrict__ x,
                  const float* __restrict__ W1,
                  const float* __restrict__ b1)
{
    __shared__ float sW1[2 * FF * HH];   // 8 KB
    __shared__ float sb1[HH];
    for (int i = threadIdx.x; i < 2 * FF * HH; i += blockDim.x) sW1[i] = W1[i];
    if (threadIdx.x < HH) sb1[threadIdx.x] = b1[threadIdx.x];
    __syncthreads();

    const int stride = gridDim.x * blockDim.x;

    // fp16 x table: 400K uint2, coalesced float4 -> 2x half2
    for (int idx = blockIdx.x * blockDim.x + threadIdx.x; idx < NN * 4; idx += stride) {
        float4 v = ((const float4*)x)[idx];
        uint2 o;
        __half2 h0 = __floats2half2_rn(v.x, v.y);
        __half2 h1 = __floats2half2_rn(v.z, v.w);
        o.x = *(unsigned*)&h0;
        o.y = *(unsigned*)&h1;
        g_Xh[idx] = o;
    }

    const int total = (NN / 4) * 32;                 // 800K (node-quad, jp)
    for (int idx = blockIdx.x * blockDim.x + threadIdx.x; idx < total; idx += stride) {
        int nq = idx >> 5;            // node quad (warp = one quad)
        int jp = idx & 31;            // half2 column pair
        int n0 = nq * 4;

        float bias0 = sb1[2 * jp], bias1 = sb1[2 * jp + 1];
        float p0[4], p1[4], q0[4], q1[4];
#pragma unroll
        for (int nn = 0; nn < 4; nn++) {
            p0[nn] = bias0; p1[nn] = bias1; q0[nn] = 0.0f; q1[nn] = 0.0f;
        }

#pragma unroll
        for (int kc = 0; kc < 4; kc++) {             // k chunk of 4
            float4 xv[4];
#pragma unroll
            for (int nn = 0; nn < 4; nn++)
                xv[nn] = ((const float4*)(x + (n0 + nn) * FF))[kc];
#pragma unroll
            for (int kk = 0; kk < 4; kk++) {
                int k = kc * 4 + kk;
                float2 wp = ((const float2*)(sW1 + k * HH))[jp];
                float2 wq = ((const float2*)(sW1 + (FF + k) * HH))[jp];
#pragma unroll
                for (int nn = 0; nn < 4; nn++) {
                    float xs = (kk == 0) ? xv[nn].x : (kk == 1) ? xv[nn].y
                             : (kk == 2) ? xv[nn].z : xv[nn].w;
                    p0[nn] = fmaf(xs, wp.x, p0[nn]);
                    p1[nn] = fmaf(xs, wp.y, p1[nn]);
                    q0[nn] = fmaf(xs, wq.x, q0[nn]);
                    q1[nn] = fmaf(xs, wq.y, q1[nn]);
                }
            }
        }
#pragma unroll
        for (int nn = 0; nn < 4; nn++) {
            int o = (n0 + nn) * 32 + jp;
            ((__half2*)g_Ph)[o] = __floats2half2_rn(p0[nn], p1[nn]);
            ((__half2*)g_Qh)[o] = __floats2half2_rn(q0[nn], q1[nn]);
        }
    }
}

// ---------------------------------------------------------------------------
// Kernel 2: EXACT R9 structure (measured best) with one change: x gathered
// from the fp16 g_Xh table (32B rows) instead of fp32 x (64B rows), cutting
// the per-edge L2 sector traffic by 64B (~14% of the gather-service floor).
// ---------------------------------------------------------------------------
__global__ void __launch_bounds__(256, 8)
edge_kernel(const float* __restrict__ x,
            const int* __restrict__ ei,        // [2, E] int32: row0=src, row1=dst
            const float* __restrict__ W2,      // [64,2] row-major
            const float* __restrict__ b2,      // [2]
            float* __restrict__ out)           // [E,16]
{
    __shared__ __half2 sWa[HH / 2];            // (wa_{2i}, wa_{2i+1}), 128B
    __shared__ __half2 sWb[HH / 2];            // (wb_{2i}, wb_{2i+1}), 128B
    if (threadIdx.x < 32) {
        int i = threadIdx.x;
        sWa[i] = __floats2half2_rn(W2[4 * i + 0], W2[4 * i + 2]);
        sWb[i] = __floats2half2_rn(W2[4 * i + 1], W2[4 * i + 3]);
    }
    __syncthreads();

    long long tid = (long long)blockIdx.x * blockDim.x + threadIdx.x;
    long long grp = tid >> 3;            // group = 2 consecutive edges
    int sub       = (int)(tid & 7);
    long long e0  = grp * 2;
    if (e0 >= EE) return;                // EE even -> e1 valid with e0

    // ---- index loads (int2: e0,e1 adjacent) ----
    int2 s01 = ((const int2*)ei)[grp];                 // src of e0,e1
    int2 d01 = ((const int2*)ei)[(EE >> 1) + grp];     // dst of e0,e1
    int src0 = s01.x, src1 = s01.y;
    int dst0 = d01.x, dst1 = d01.y;

    // ---- front-batched gathers ----
    uint4 pu0 = g_Ph[(size_t)dst0 * (HH / 8) + sub];
    uint4 qu0 = g_Qh[(size_t)src0 * (HH / 8) + sub];
    uint4 pu1 = g_Ph[(size_t)dst1 * (HH / 8) + sub];
    uint4 qu1 = g_Qh[(size_t)src1 * (HH / 8) + sub];

    bool lo = (sub < 4);
    int dN = lo ? dst0 : dst1;
    int sN = lo ? src0 : src1;
    int c  = sub & 3;
    uint2 xdu = g_Xh[(size_t)dN * 4 + c];    // 4 halves of x_dst
    uint2 xsu = g_Xh[(size_t)sN * 4 + c];    // 4 halves of x_src

    // ---- weights for this lane's j = 8*sub .. 8*sub+7 (1 LDS.128 each) ----
    uint4 wau = *(const uint4*)(sWa + 4 * sub);
    uint4 wbu = *(const uint4*)(sWb + 4 * sub);
    const __half2* wa = (const __half2*)&wau;
    const __half2* wb = (const __half2*)&wbu;

    // ---- packed half2 dots ----
    const __half2* ph0 = (const __half2*)&pu0;
    const __half2* qh0 = (const __half2*)&qu0;
    const __half2* ph1 = (const __half2*)&pu1;
    const __half2* qh1 = (const __half2*)&qu1;
    const __half2 z2 = __float2half2_rn(0.0f);
    __half2 avh0 = z2, bvh0 = z2, avh1 = z2, bvh1 = z2;
#pragma unroll
    for (int t = 0; t < 4; t++) {
        __half2 hh0 = __hmax2(__hadd2(ph0[t], qh0[t]), z2);
        __half2 hh1 = __hmax2(__hadd2(ph1[t], qh1[t]), z2);
        avh0 = __hfma2(hh0, wa[t], avh0);
        bvh0 = __hfma2(hh0, wb[t], bvh0);
        avh1 = __hfma2(hh1, wa[t], avh1);
        bvh1 = __hfma2(hh1, wb[t], bvh1);
    }
    float2 fa0 = __half22float2(avh0);
    float2 fb0 = __half22float2(bvh0);
    float2 fa1 = __half22float2(avh1);
    float2 fb1 = __half22float2(bvh1);
    float av0 = fa0.x + fa0.y, bv0 = fb0.x + fb0.y;
    float av1 = fa1.x + fa1.y, bv1 = fb1.x + fb1.y;

    // ---- reduce: 2 butterfly rounds, then select-swap across halves (R9) ----
#pragma unroll
    for (int m = 1; m < 4; m <<= 1) {
        av0 += __shfl_xor_sync(0xffffffffu, av0, m);
        bv0 += __shfl_xor_sync(0xffffffffu, bv0, m);
        av1 += __shfl_xor_sync(0xffffffffu, av1, m);
        bv1 += __shfl_xor_sync(0xffffffffu, bv1, m);
    }
    float va = lo ? av1 : av0;
    float vb = lo ? bv1 : bv0;
    float ra = __shfl_xor_sync(0xffffffffu, va, 4);
    float rb = __shfl_xor_sync(0xffffffffu, vb, 4);
    float a  = (lo ? av0 : av1) + ra + b2[0];
    float b  = (lo ? bv0 : bv1) + rb + b2[1];

    // ---- epilogue: unpack fp16 x, lane owns 4 floats of its edge ----
    float2 xd01 = __half22float2(*(const __half2*)&xdu.x);
    float2 xd23 = __half22float2(*(const __half2*)&xdu.y);
    float2 xs01 = __half22float2(*(const __half2*)&xsu.x);
    float2 xs23 = __half22float2(*(const __half2*)&xsu.y);

    long long e = lo ? e0 : (e0 + 1);
    float4 o;
    o.x = a * (xd01.x - b * xs01.x);
    o.y = a * (xd01.y - b * xs01.y);
    o.z = a * (xd23.x - b * xs23.x);
    o.w = a * (xd23.y - b * xs23.y);
    ((float4*)(out + (size_t)e * FF))[c] = o;
    (void)x;
}

// ---------------------------------------------------------------------------
// Launch
// ---------------------------------------------------------------------------
extern "C" void kernel_launch(void* const* d_in, const int* in_sizes, int n_in,
                              void* d_out, int out_size)
{
    const float* x   = (const float*)d_in[0];   // [N,16]
    const int*   ei  = (const int*)d_in[1];     // [2,E] int32
    const float* W1  = (const float*)d_in[2];   // [32,64]
    const float* b1  = (const float*)d_in[3];   // [64]
    const float* W2  = (const float*)d_in[4];   // [64,2]
    const float* b2  = (const float*)d_in[5];   // [2]
    float*       out = (float*)d_out;           // [E,16]

    (void)in_sizes; (void)n_in; (void)out_size;

    precompute_kernel<<<1184, 256>>>(x, W1, b1);

    {
        long long total = (long long)(EE / 2) * 8;   // 12.8M threads
        int threads = 256;
        int blocks = (int)((total + threads - 1) / threads);
        edge_kernel<<<blocks, threads>>>(x, ei, W2, b2, out);
    }
}

// round 14
// speedup vs baseline: 1.0293x; 1.0130x over previous
#include <cuda_runtime.h>
#include <cuda_fp16.h>

// Problem constants: N=100000, F=16, E=3200000, H=64
#define NN 100000
#define FF 16
#define EE 3200000
#define HH 64

// fp16 scratch tables, one 128-byte row per node (64 halves).
// P[n][j] = sum_k x[n][k]*W1[k][j] + b1[j]   (dst half of concat)
// Q[n][j] = sum_k x[n][k]*W1[16+k][j]        (src half of concat)
__device__ uint4 g_Ph[(size_t)NN * (HH / 8)];   // 12.8 MB
__device__ uint4 g_Qh[(size_t)NN * (HH / 8)];
// fp16 copy of x: 16 halves = 32B per node, chunk c holds halves 4c..4c+3.
__device__ uint2 g_Xh[(size_t)NN * 4];          // 3.2 MB

// ---------------------------------------------------------------------------
// Kernel 1: precompute P,Q in fp16; x-fp16 conversion folded into the same
// node-quad loop (lanes 0-15 convert the quad's 64 x floats from L1-resident
// rows -> one coalesced 128B store), removing the separate conversion pass.
// ---------------------------------------------------------------------------
__global__ void __launch_bounds__(256)
precompute_kernel(const float* __restrict__ x,
                  const float* __restrict__ W1,
                  const float* __restrict__ b1)
{
    __shared__ float sW1[2 * FF * HH];   // 8 KB
    __shared__ float sb1[HH];
    for (int i = threadIdx.x; i < 2 * FF * HH; i += blockDim.x) sW1[i] = W1[i];
    if (threadIdx.x < HH) sb1[threadIdx.x] = b1[threadIdx.x];
    __syncthreads();

    const int total  = (NN / 4) * 32;                // 800K (node-quad, jp)
    const int stride = gridDim.x * blockDim.x;
    for (int idx = blockIdx.x * blockDim.x + threadIdx.x; idx < total; idx += stride) {
        int nq = idx >> 5;            // node quad (warp = one quad)
        int jp = idx & 31;            // half2 column pair
        int n0 = nq * 4;

        float bias0 = sb1[2 * jp], bias1 = sb1[2 * jp + 1];
        float p0[4], p1[4], q0[4], q1[4];
#pragma unroll
        for (int nn = 0; nn < 4; nn++) {
            p0[nn] = bias0; p1[nn] = bias1; q0[nn] = 0.0f; q1[nn] = 0.0f;
        }

#pragma unroll
        for (int kc = 0; kc < 4; kc++) {             // k chunk of 4
            float4 xv[4];
#pragma unroll
            for (int nn = 0; nn < 4; nn++)
                xv[nn] = ((const float4*)(x + (n0 + nn) * FF))[kc];
#pragma unroll
            for (int kk = 0; kk < 4; kk++) {
                int k = kc * 4 + kk;
                float2 wp = ((const float2*)(sW1 + k * HH))[jp];
                float2 wq = ((const float2*)(sW1 + (FF + k) * HH))[jp];
#pragma unroll
                for (int nn = 0; nn < 4; nn++) {
                    float xs = (kk == 0) ? xv[nn].x : (kk == 1) ? xv[nn].y
                             : (kk == 2) ? xv[nn].z : xv[nn].w;
                    p0[nn] = fmaf(xs, wp.x, p0[nn]);
                    p1[nn] = fmaf(xs, wp.y, p1[nn]);
                    q0[nn] = fmaf(xs, wq.x, q0[nn]);
                    q1[nn] = fmaf(xs, wq.y, q1[nn]);
                }
            }
        }
#pragma unroll
        for (int nn = 0; nn < 4; nn++) {
            int o = (n0 + nn) * 32 + jp;
            ((__half2*)g_Ph)[o] = __floats2half2_rn(p0[nn], p1[nn]);
            ((__half2*)g_Qh)[o] = __floats2half2_rn(q0[nn], q1[nn]);
        }

        // fold: convert the quad's x (64 floats = 16 float4) to fp16.
        // Rows are L1-resident from the loads above; store is 128B coalesced.
        if (jp < 16) {
            float4 v = ((const float4*)(x + n0 * FF))[jp];
            __half2 h0 = __floats2half2_rn(v.x, v.y);
            __half2 h1 = __floats2half2_rn(v.z, v.w);
            uint2 o;
            o.x = *(unsigned*)&h0;
            o.y = *(unsigned*)&h1;
            g_Xh[n0 * 4 + jp] = o;
        }
    }
}

// ---------------------------------------------------------------------------
// Kernel 2: unchanged from R13 (best measured edge kernel, 120.4us).
// 8 lanes/group, 2 edges/group, packed half2 dots, fp16 x gather (32B rows).
// ---------------------------------------------------------------------------
__global__ void __launch_bounds__(256, 8)
edge_kernel(const float* __restrict__ x,
            const int* __restrict__ ei,        // [2, E] int32: row0=src, row1=dst
            const float* __restrict__ W2,      // [64,2] row-major
            const float* __restrict__ b2,      // [2]
            float* __restrict__ out)           // [E,16]
{
    __shared__ __half2 sWa[HH / 2];            // (wa_{2i}, wa_{2i+1}), 128B
    __shared__ __half2 sWb[HH / 2];            // (wb_{2i}, wb_{2i+1}), 128B
    if (threadIdx.x < 32) {
        int i = threadIdx.x;
        sWa[i] = __floats2half2_rn(W2[4 * i + 0], W2[4 * i + 2]);
        sWb[i] = __floats2half2_rn(W2[4 * i + 1], W2[4 * i + 3]);
    }
    __syncthreads();

    long long tid = (long long)blockIdx.x * blockDim.x + threadIdx.x;
    long long grp = tid >> 3;            // group = 2 consecutive edges
    int sub       = (int)(tid & 7);
    long long e0  = grp * 2;
    if (e0 >= EE) return;                // EE even -> e1 valid with e0

    // ---- index loads (int2: e0,e1 adjacent) ----
    int2 s01 = ((const int2*)ei)[grp];                 // src of e0,e1
    int2 d01 = ((const int2*)ei)[(EE >> 1) + grp];     // dst of e0,e1
    int src0 = s01.x, src1 = s01.y;
    int dst0 = d01.x, dst1 = d01.y;

    // ---- front-batched gathers ----
    uint4 pu0 = g_Ph[(size_t)dst0 * (HH / 8) + sub];
    uint4 qu0 = g_Qh[(size_t)src0 * (HH / 8) + sub];
    uint4 pu1 = g_Ph[(size_t)dst1 * (HH / 8) + sub];
    uint4 qu1 = g_Qh[(size_t)src1 * (HH / 8) + sub];

    bool lo = (sub < 4);
    int dN = lo ? dst0 : dst1;
    int sN = lo ? src0 : src1;
    int c  = sub & 3;
    uint2 xdu = g_Xh[(size_t)dN * 4 + c];    // 4 halves of x_dst
    uint2 xsu = g_Xh[(size_t)sN * 4 + c];    // 4 halves of x_src

    // ---- weights for this lane's j = 8*sub .. 8*sub+7 (1 LDS.128 each) ----
    uint4 wau = *(const uint4*)(sWa + 4 * sub);
    uint4 wbu = *(const uint4*)(sWb + 4 * sub);
    const __half2* wa = (const __half2*)&wau;
    const __half2* wb = (const __half2*)&wbu;

    // ---- packed half2 dots ----
    const __half2* ph0 = (const __half2*)&pu0;
    const __half2* qh0 = (const __half2*)&qu0;
    const __half2* ph1 = (const __half2*)&pu1;
    const __half2* qh1 = (const __half2*)&qu1;
    const __half2 z2 = __float2half2_rn(0.0f);
    __half2 avh0 = z2, bvh0 = z2, avh1 = z2, bvh1 = z2;
#pragma unroll
    for (int t = 0; t < 4; t++) {
        __half2 hh0 = __hmax2(__hadd2(ph0[t], qh0[t]), z2);
        __half2 hh1 = __hmax2(__hadd2(ph1[t], qh1[t]), z2);
        avh0 = __hfma2(hh0, wa[t], avh0);
        bvh0 = __hfma2(hh0, wb[t], bvh0);
        avh1 = __hfma2(hh1, wa[t], avh1);
        bvh1 = __hfma2(hh1, wb[t], bvh1);
    }
    float2 fa0 = __half22float2(avh0);
    float2 fb0 = __half22float2(bvh0);
    float2 fa1 = __half22float2(avh1);
    float2 fb1 = __half22float2(bvh1);
    float av0 = fa0.x + fa0.y, bv0 = fb0.x + fb0.y;
    float av1 = fa1.x + fa1.y, bv1 = fb1.x + fb1.y;

    // ---- reduce: 2 butterfly rounds, then select-swap across halves ----
#pragma unroll
    for (int m = 1; m < 4; m <<= 1) {
        av0 += __shfl_xor_sync(0xffffffffu, av0, m);
        bv0 += __shfl_xor_sync(0xffffffffu, bv0, m);
        av1 += __shfl_xor_sync(0xffffffffu, av1, m);
        bv1 += __shfl_xor_sync(0xffffffffu, bv1, m);
    }
    float va = lo ? av1 : av0;
    float vb = lo ? bv1 : bv0;
    float ra = __shfl_xor_sync(0xffffffffu, va, 4);
    float rb = __shfl_xor_sync(0xffffffffu, vb, 4);
    float a  = (lo ? av0 : av1) + ra + b2[0];
    float b  = (lo ? bv0 : bv1) + rb + b2[1];

    // ---- epilogue: unpack fp16 x, lane owns 4 floats of its edge ----
    float2 xd01 = __half22float2(*(const __half2*)&xdu.x);
    float2 xd23 = __half22float2(*(const __half2*)&xdu.y);
    float2 xs01 = __half22float2(*(const __half2*)&xsu.x);
    float2 xs23 = __half22float2(*(const __half2*)&xsu.y);

    long long e = lo ? e0 : (e0 + 1);
    float4 o;
    o.x = a * (xd01.x - b * xs01.x);
    o.y = a * (xd01.y - b * xs01.y);
    o.z = a * (xd23.x - b * xs23.x);
    o.w = a * (xd23.y - b * xs23.y);
    ((float4*)(out + (size_t)e * FF))[c] = o;
    (void)x;
}

// ---------------------------------------------------------------------------
// Launch
// ---------------------------------------------------------------------------
extern "C" void kernel_launch(void* const* d_in, const int* in_sizes, int n_in,
                              void* d_out, int out_size)
{
    const float* x   = (const float*)d_in[0];   // [N,16]
    const int*   ei  = (const int*)d_in[1];     // [2,E] int32
    const float* W1  = (const float*)d_in[2];   // [32,64]
    const float* b1  = (const float*)d_in[3];   // [64]
    const float* W2  = (const float*)d_in[4];   // [64,2]
    const float* b2  = (const float*)d_in[5];   // [2]
    float*       out = (float*)d_out;           // [E,16]

    (void)in_sizes; (void)n_in; (void)out_size;

    precompute_kernel<<<1184, 256>>>(x, W1, b1);

    {
        long long total = (long long)(EE / 2) * 8;   // 12.8M threads
        int threads = 256;
        int blocks = (int)((total + threads - 1) / threads);
        edge_kernel<<<blocks, threads>>>(x, ei, W2, b2, out);
    }
}